// round 15
// baseline (speedup 1.0000x reference)
#include <cuda_runtime.h>
#include <cuda_fp16.h>
#include <math.h>
#include <stdint.h>

// ---------------- problem constants ----------------
#define T_LEN 1024
#define HID   2048
#define NH    12
#define DK    128
#define DV    256
#define KDIM  1536
#define VDIM  3072
#define PROJN 9216
#define PROJN_PAD 9344
// fp16 2-term split: A stored [hi|lo] (2*K), B stored [hi] (K).
#define KA1 (2*HID)
#define KB1 (HID)
#define KA2 (2*VDIM)
#define KB2 (VDIM)

// ---------------- scratch ----------------
constexpr size_t SZ_PROJ = (size_t)T_LEN * PROJN_PAD * 4;
constexpr size_t SZ_A3   = (size_t)T_LEN * KA1 * 2;
constexpr size_t SZ_B3   = (size_t)PROJN_PAD * KB1 * 2;
constexpr size_t SZ_A2   = (size_t)T_LEN * KA2 * 2;
constexpr size_t SZ_B2   = (size_t)HID * KB2 * 2;
constexpr size_t SZ_QK   = (size_t)T_LEN * KDIM * 4;
constexpr size_t SZ_V    = (size_t)T_LEN * VDIM * 4;
constexpr size_t SZ_H    = (size_t)T_LEN * NH * 4;
constexpr size_t SZ_CP   = (size_t)2 * T_LEN * HID * 4;

constexpr size_t B_PROJ = 0;
constexpr size_t B_A3   = B_PROJ + SZ_PROJ;
constexpr size_t B_B3   = B_A3 + SZ_A3;
constexpr size_t B_A2   = B_B3 + SZ_B3;
constexpr size_t B_B2   = B_A2 + SZ_A2;
constexpr size_t B_Q    = B_B2 + SZ_B2;
constexpr size_t B_K    = B_Q + SZ_QK;
constexpr size_t B_V    = B_K + SZ_QK;
constexpr size_t B_O    = B_V + SZ_V;
constexpr size_t B_G    = B_O + SZ_V;
constexpr size_t B_BB   = B_G + SZ_H;
constexpr size_t B_CP   = B_BB + SZ_H;
constexpr size_t SCRATCH_BYTES = B_CP + SZ_CP;

__device__ __align__(256) unsigned char g_scratch[SCRATCH_BYTES];

// pair table: p<28 -> K pair (si,ss) s<i ; p>=28 -> Q pair (si,ss) s<=i
// enc = (isQ<<6) | (si<<3) | ss
__constant__ unsigned char PAIR_TAB[64] = {
    0x08,
    0x10,0x11,
    0x18,0x19,0x1a,
    0x20,0x21,0x22,0x23,
    0x28,0x29,0x2a,0x2b,0x2c,
    0x30,0x31,0x32,0x33,0x34,0x35,
    0x38,0x39,0x3a,0x3b,0x3c,0x3d,0x3e,
    0x40,
    0x48,0x49,
    0x50,0x51,0x52,
    0x58,0x59,0x5a,0x5b,
    0x60,0x61,0x62,0x63,0x64,
    0x68,0x69,0x6a,0x6b,0x6c,0x6d,
    0x70,0x71,0x72,0x73,0x74,0x75,0x76,
    0x78,0x79,0x7a,0x7b,0x7c,0x7d,0x7e,0x7f
};
#define TK(i,s) ((i)*((i)-1)/2 + (s))
#define TQ(i,s) (28 + (i)*((i)+1)/2 + (s))

// ---------------- PTX helpers ----------------
__device__ __forceinline__ uint32_t smem_u32(const void* p) {
    uint32_t a;
    asm("{ .reg .u64 t; cvta.to.shared.u64 t, %1; cvt.u32.u64 %0, t; }" : "=r"(a) : "l"(p));
    return a;
}
__device__ __forceinline__ void cpasync16(uint32_t dst, const void* src) {
    asm volatile("cp.async.cg.shared.global [%0], [%1], 16;" :: "r"(dst), "l"(src) : "memory");
}
#define CP_COMMIT() asm volatile("cp.async.commit_group;" ::: "memory")
#define CP_WAIT0()  asm volatile("cp.async.wait_group 0;" ::: "memory")
#define CP_WAIT1()  asm volatile("cp.async.wait_group 1;" ::: "memory")

__device__ __forceinline__ void ldm4(uint32_t* r, uint32_t addr) {
    asm volatile("ldmatrix.sync.aligned.m8n8.x4.shared.b16 {%0,%1,%2,%3}, [%4];"
        : "=r"(r[0]), "=r"(r[1]), "=r"(r[2]), "=r"(r[3]) : "r"(addr));
}
__device__ __forceinline__ void mma16816(float* c, const uint32_t* a, uint32_t b0, uint32_t b1) {
    asm volatile("mma.sync.aligned.m16n8k16.row.col.f32.f16.f16.f32 "
        "{%0,%1,%2,%3}, {%4,%5,%6,%7}, {%8,%9}, {%0,%1,%2,%3};"
        : "+f"(c[0]), "+f"(c[1]), "+f"(c[2]), "+f"(c[3])
        : "r"(a[0]), "r"(a[1]), "r"(a[2]), "r"(a[3]), "r"(b0), "r"(b1));
}
#define SWZ128(o) ((o) ^ (((o) >> 3) & 0x70))

// ---------------- fp16 mma.sync GEMM (proven R10 config): CTA 128x128, 3-stage ----------------
#define GEMM_SMEM 98304

__global__ __launch_bounds__(256, 2) void gemm_f16(
    const __half* __restrict__ A, const __half* __restrict__ Bt,
    float* __restrict__ C, int M, int N, int KA, int KB, int P, int chunksPerZ)
{
    extern __shared__ unsigned char smem_raw[];
    uint32_t sb = smem_u32(smem_raw);

    const int tid  = threadIdx.x;
    const int wid  = tid >> 5;
    const int lane = tid & 31;
    const int wm   = wid & 3;
    const int wn   = wid >> 2;

    const int bm = blockIdx.x * 128;
    const int bn = blockIdx.y * 128;
    const int gcBase = blockIdx.z * chunksPerZ;
    float* Cz = C + (size_t)blockIdx.z * M * N;

    const int lrow = tid >> 1;
    const int lcolB = (tid & 1) * 64;
    const __half* Arow = A + (size_t)(bm + lrow) * KA;
    const __half* Brow = Bt + (size_t)(bn + lrow) * KB;
    uint32_t st[4];
#pragma unroll
    for (int j = 0; j < 4; j++) {
        uint32_t o = (uint32_t)lrow * 128u + (uint32_t)lcolB + j * 16u;
        st[j] = SWZ128(o);
    }

    const int l8 = lane & 7;
    const int rowA = wm * 32 + ((lane >> 3) & 1) * 8 + l8;
    const uint32_t colA = (uint32_t)((lane >> 4) * 16);
    const uint32_t xorA = (uint32_t)((rowA & 7) << 4);
    const int rowB = wn * 64 + ((lane >> 4) & 1) * 8 + l8;
    const uint32_t colB = (uint32_t)(((lane >> 3) & 1) * 16);
    const uint32_t xorB = (uint32_t)((rowB & 7) << 4);

    float c[2][8][4];
#pragma unroll
    for (int mf = 0; mf < 2; mf++)
#pragma unroll
        for (int nf = 0; nf < 8; nf++)
#pragma unroll
            for (int i = 0; i < 4; i++) c[mf][nf][i] = 0.f;

    auto issue = [&](int gc, int s) {
        int bc = (gc < P) ? gc : gc - P;
        const unsigned char* Ag = (const unsigned char*)(Arow + gc * 64);
        const unsigned char* Bg = (const unsigned char*)(Brow + bc * 64);
        uint32_t ab = sb + (uint32_t)s * 32768u;
        uint32_t bb = ab + 16384u;
#pragma unroll
        for (int j = 0; j < 4; j++) cpasync16(ab + st[j], Ag + lcolB + j * 16);
#pragma unroll
        for (int j = 0; j < 4; j++) cpasync16(bb + st[j], Bg + lcolB + j * 16);
    };

#pragma unroll
    for (int p = 0; p < 2; p++) {
        issue(gcBase + p, p);
        CP_COMMIT();
    }

    int sc = 0;
    int sp = 2;

    for (int i = 0; i < chunksPerZ; i++) {
        CP_WAIT1();
        __syncthreads();

        if (i + 2 < chunksPerZ) issue(gcBase + i + 2, sp);
        CP_COMMIT();

        uint32_t ab = sb + (uint32_t)sc * 32768u;
        uint32_t bb = ab + 16384u;
#pragma unroll
        for (int ks = 0; ks < 4; ks++) {
            uint32_t af0[4], af1[4];
            uint32_t ac = ((uint32_t)(ks * 32) + colA) ^ xorA;
            ldm4(af0, ab + (uint32_t)rowA * 128u + ac);
            ldm4(af1, ab + (uint32_t)rowA * 128u + 2048u + ac);

            uint32_t bf[4][4];
            uint32_t bc = ((uint32_t)(ks * 32) + colB) ^ xorB;
#pragma unroll
            for (int p = 0; p < 4; p++)
                ldm4(bf[p], bb + (uint32_t)(rowB + p * 16) * 128u + bc);

#pragma unroll
            for (int nf = 0; nf < 8; nf++) {
                uint32_t b0 = bf[nf >> 1][(nf & 1) * 2 + 0];
                uint32_t b1 = bf[nf >> 1][(nf & 1) * 2 + 1];
                mma16816(c[0][nf], af0, b0, b1);
                mma16816(c[1][nf], af1, b0, b1);
            }
        }

        sc = (sc == 2) ? 0 : sc + 1;
        sp = (sp == 2) ? 0 : sp + 1;
    }

    const int g  = lane >> 2;
    const int t4 = lane & 3;
#pragma unroll
    for (int mf = 0; mf < 2; mf++) {
#pragma unroll
        for (int nf = 0; nf < 8; nf++) {
            int row = bm + wm * 32 + mf * 16 + g;
            int col = bn + wn * 64 + nf * 8 + t4 * 2;
            *(float2*)(Cz + (size_t)row * N + col)       = make_float2(c[mf][nf][0], c[mf][nf][1]);
            *(float2*)(Cz + (size_t)(row + 8) * N + col) = make_float2(c[mf][nf][2], c[mf][nf][3]);
        }
    }
}

__global__ __launch_bounds__(256) void combine_kernel(const float* __restrict__ c01, float* __restrict__ out)
{
    int i = blockIdx.x * 256 + threadIdx.x;
    out[i] = c01[i] + c01[i + (size_t)T_LEN * HID];
}

// ---------------- fp16 hi/lo split ----------------
__device__ __forceinline__ void f16split(float x, __half& hi, __half& lo) {
    hi = __float2half_rn(x);
    lo = __float2half_rn(x - __half2float(hi));
}

// ---------------- merged prep kernel ----------------
#define NB_SPLIT 2048
#define NB_TSP   ((HID/64)*(PROJN_PAD/32))
#define NB_TSW   ((VDIM/64)*(HID/32))

__device__ void split_hs_body(const float* __restrict__ hs, __half* __restrict__ A3, int b)
{
    int idx = b * 256 + threadIdx.x;
    int t = idx >> 9;
    int kq = (idx & 511) * 4;
    float4 x = *(const float4*)(hs + (size_t)t * HID + kq);
    __half2 h01, h23, l01, l23;
    __half h, l;
    f16split(x.x, h, l); h01.x = h; l01.x = l;
    f16split(x.y, h, l); h01.y = h; l01.y = l;
    f16split(x.z, h, l); h23.x = h; l23.x = l;
    f16split(x.w, h, l); h23.y = h; l23.y = l;
    __half* row = A3 + (size_t)t * KA1;
    *(__half2*)(row + kq)           = h01;
    *(__half2*)(row + kq + 2)       = h23;
    *(__half2*)(row + HID + kq)     = l01;
    *(__half2*)(row + HID + kq + 2) = l23;
}

template<int KW>
__device__ __forceinline__ void tstore_tile(
    const float* tileflat, int k0, int n0, __half* Bout)
{
    const float (*tile)[72] = (const float (*)[72])tileflat;
    int tid = threadIdx.x;
#pragma unroll
    for (int pass = 0; pass < 4; pass++) {
        int nl = (tid >> 5) + pass * 8;
        int kl = (tid & 31) * 2;
        __half2 hp;
        hp.x = __float2half_rn(tile[nl][kl]);
        hp.y = __float2half_rn(tile[nl][kl + 1]);
        *reinterpret_cast<__half2*>(Bout + (size_t)(n0 + nl) * KW + k0 + kl) = hp;
    }
}

__device__ void tsplit_proj_body(
    const float* __restrict__ Wq, const float* __restrict__ Wk,
    const float* __restrict__ Wv, const float* __restrict__ Wg,
    const float* __restrict__ Wb, const float* __restrict__ Wa,
    __half* __restrict__ B3, int bx, int by)
{
    __shared__ float tile[32][72];
    int k0 = bx * 64, n0 = by * 32;
    int tid = threadIdx.x;
    int nl = tid & 31, n = n0 + nl;
#pragma unroll
    for (int i = 0; i < 8; i++) {
        int k = k0 + (tid >> 5) + i * 8;
        float v;
        if      (n < KDIM)            v = Wq[(size_t)k * KDIM + n];
        else if (n < 2 * KDIM)        v = Wk[(size_t)k * KDIM + n - KDIM];
        else if (n < 2 * KDIM + VDIM) v = Wv[(size_t)k * VDIM + n - 2 * KDIM];
        else if (n < PROJN)           v = Wg[(size_t)k * VDIM + n - 2 * KDIM - VDIM];
        else if (n < PROJN + NH)      v = Wb[(size_t)k * NH + n - PROJN];
        else if (n < PROJN + 2 * NH)  v = Wa[(size_t)k * NH + n - PROJN - NH];
        else                          v = 0.f;
        tile[nl][(tid >> 5) + i * 8] = v;
    }
    __syncthreads();
    tstore_tile<KB1>(&tile[0][0], k0, n0, B3);
}

__device__ void tsplit_wo_body(const float* __restrict__ Wo, __half* __restrict__ B2, int bx, int by)
{
    __shared__ float tile[32][72];
    int k0 = bx * 64, n0 = by * 32;
    int tid = threadIdx.x;
    int nl = tid & 31;
#pragma unroll
    for (int i = 0; i < 8; i++) {
        int k = k0 + (tid >> 5) + i * 8;
        tile[nl][(tid >> 5) + i * 8] = Wo[(size_t)k * HID + n0 + nl];
    }
    __syncthreads();
    tstore_tile<KB2>(&tile[0][0], k0, n0, B2);
}

__global__ __launch_bounds__(256) void prep_all(
    const float* __restrict__ hs,
    const float* __restrict__ Wq, const float* __restrict__ Wk,
    const float* __restrict__ Wv, const float* __restrict__ Wg,
    const float* __restrict__ Wb, const float* __restrict__ Wa,
    const float* __restrict__ Wo,
    __half* __restrict__ A3, __half* __restrict__ B3, __half* __restrict__ B2)
{
    int b = blockIdx.x;
    if (b < NB_SPLIT) {
        split_hs_body(hs, A3, b);
    } else if (b < NB_SPLIT + NB_TSP) {
        int bb = b - NB_SPLIT;
        tsplit_proj_body(Wq, Wk, Wv, Wg, Wb, Wa, B3, bb % (HID / 64), bb / (HID / 64));
    } else {
        int bb = b - NB_SPLIT - NB_TSP;
        tsplit_wo_body(Wo, B2, bb % (VDIM / 64), bb / (VDIM / 64));
    }
}

// ---------------- fused conv (+ beta/g fold on h==0 blocks) ----------------
__global__ __launch_bounds__(256) void conv_fused(
    const float* __restrict__ proj,
    const float* __restrict__ wq, const float* __restrict__ wk, const float* __restrict__ wv,
    const float* __restrict__ A_log, const float* __restrict__ dt_bias,
    float* __restrict__ qo, float* __restrict__ ko, float* __restrict__ vo,
    float* __restrict__ beta, float* __restrict__ egout)
{
    int t = blockIdx.x, h = blockIdx.y;
    int d = threadIdx.x;
    int which = d >> 7;
    int dd = d & 127;
    int ch = h * DK + dd;

    const float* w = which ? wk : wq;
    int cqk = (which ? KDIM : 0) + ch;
    int cv  = 2 * KDIM + h * DV + d;

    float y = 0.f, yv = 0.f;
#pragma unroll
    for (int i = 0; i < 4; i++) {
        int tt = t - 3 + i;
        if (tt >= 0) {
            const float* prow = proj + (size_t)tt * PROJN_PAD;
            y  = fmaf(prow[cqk], w[ch * 4 + i], y);
            yv = fmaf(prow[cv], wv[(h * DV + d) * 4 + i], yv);
        }
    }
    y  = y / (1.f + expf(-y));
    yv = yv / (1.f + expf(-yv));

    float ss = y * y;
#pragma unroll
    for (int off = 16; off; off >>= 1)
        ss += __shfl_xor_sync(0xffffffffu, ss, off);
    __shared__ float red[8];
    int lane = d & 31, warp = d >> 5;
    if (lane == 0) red[warp] = ss;
    __syncthreads();
    float tot = red[which * 4 + 0] + red[which * 4 + 1] + red[which * 4 + 2] + red[which * 4 + 3];

    float* dst = which ? ko : qo;
    dst[(size_t)t * KDIM + ch] = y * rsqrtf(tot + 1e-6f);
    vo[(size_t)t * VDIM + h * DV + d] = yv;

    if (h == 0 && d < 24) {
        float sv = proj[(size_t)t * PROJN_PAD + PROJN + d];
        if (d < NH) {
            beta[t * NH + d] = 1.f / (1.f + expf(-sv));
        } else {
            int hh = d - NH;
            float x = sv + dt_bias[hh];
            float sp = (x > 20.f) ? x : log1pf(expf(x));
            egout[t * NH + hh] = expf(-expf(A_log[hh]) * sp);
        }
    }
}

// ---------------- block-processed gated delta-rule scan (B=8), v5 ----------------
// 256 threads: j=lane (column), g=warp (16 k-rows). 3 barriers/block:
//   - triangular pair set (64 dots instead of 128)
//   - state update deferred into next block (barrier C eliminated)
#define NBLK 128

__global__ __launch_bounds__(256, 1) void scan_block_kernel(
    const float* __restrict__ q, const float* __restrict__ k,
    const float* __restrict__ v, const float* __restrict__ eg_in,
    const float* __restrict__ bb, float* __restrict__ o)
{
    const int h = blockIdx.x >> 3;
    const int chunk = blockIdx.x & 7;
    const int tid = threadIdx.x;
    const int j = tid & 31;
    const int g = tid >> 5;
    const int G = g * 16;

    __shared__ float kqsh[2][2][8][128];   // [0=k,1=q][buf][step][dim]
    __shared__ float vsh[2][8][32];
    __shared__ float egb[2][2][8];
    __shared__ float pdk[8][32 * 9];
    __shared__ float pdq[8][32 * 9];
    __shared__ float psc[64][9];
    __shared__ float ar[8][33], br[8][33];
    __shared__ float scal[64];
    __shared__ float wsh[8][32];
    __shared__ float E7sh;

    float S[16];
#pragma unroll
    for (int i = 0; i < 16; i++) S[i] = 0.f;
    float4 kr[8][4];

    const int kq_base = h * DK;
    const int v_base  = h * DV + chunk * 32;

    const int ki  = tid >> 5;
    const int kf  = (tid & 31) * 4;
    const int vi  = tid >> 3;
    const int vf  = (tid & 7) * 4;
    uint32_t kdst[2], qdst[2], vdst[2];
#pragma unroll
    for (int p = 0; p < 2; p++) {
        kdst[p] = smem_u32(&kqsh[0][p][ki][kf]);
        qdst[p] = smem_u32(&kqsh[1][p][ki][kf]);
        vdst[p] = smem_u32(&vsh[p][0][0]) + (uint32_t)(vi * 32 + vf) * 4u;
    }

    const int eb_i = tid - 192;
    float pebs = 0.f;
    if (eb_i >= 0 && eb_i < 16) {
        int i0 = eb_i & 7;
        pebs = (eb_i < 8) ? eg_in[(size_t)i0 * NH + h] : bb[(size_t)i0 * NH + h];
    }

    // decode my two pair-table entries (loop-invariant)
    const unsigned e0 = PAIR_TAB[j];
    const unsigned e1 = PAIR_TAB[j + 32];
    const int q0_ = e0 >> 6, si0 = (e0 >> 3) & 7, ss0 = e0 & 7;
    const int q1_ = e1 >> 6, si1 = (e1 >> 3) & 7, ss1 = e1 & 7;

    {
        cpasync16(kdst[0], k + (size_t)ki * KDIM + kq_base + kf);
        cpasync16(qdst[0], q + (size_t)ki * KDIM + kq_base + kf);
        if (tid < 64) cpasync16(vdst[0], v + (size_t)vi * VDIM + v_base + vf);
        CP_COMMIT();
    }

    for (int b = 0; b < NBLK; b++) {
        const int buf = b & 1;
        const int t0 = b * 8;

        CP_WAIT0();
        if (eb_i >= 0 && eb_i < 16)
            egb[buf][eb_i >> 3][eb_i & 7] = pebs;
        __syncthreads();                                   // (A) data + prev solver results visible

        if (b + 1 < NBLK) {
            const int nb = (b + 1) & 1;
            const size_t r0 = (size_t)(t0 + 8);
            cpasync16(kdst[nb], k + (r0 + ki) * KDIM + kq_base + kf);
            cpasync16(qdst[nb], q + (r0 + ki) * KDIM + kq_base + kf);
            if (tid < 64) cpasync16(vdst[nb], v + (r0 + vi) * VDIM + v_base + vf);
            if (eb_i >= 0 && eb_i < 16) {
                int i0 = eb_i & 7;
                pebs = (eb_i < 8) ? eg_in[(r0 + i0) * NH + h] : bb[(r0 + i0) * NH + h];
            }
            CP_COMMIT();
        }

        // ---- deferred P5: apply previous block's rank-8 update (uses old kr) ----
        if (b > 0) {
            float E7 = E7sh;
            float w[8];
#pragma unroll
            for (int s = 0; s < 8; s++) w[s] = wsh[s][j];
#pragma unroll
            for (int r = 0; r < 16; r++) S[r] *= E7;
#pragma unroll
            for (int s = 0; s < 8; s++) {
#pragma unroll
                for (int r4 = 0; r4 < 4; r4++) {
                    float4 kv = kr[s][r4];
                    S[r4*4+0] = fmaf(kv.x, w[s], S[r4*4+0]);
                    S[r4*4+1] = fmaf(kv.y, w[s], S[r4*4+1]);
                    S[r4*4+2] = fmaf(kv.z, w[s], S[r4*4+2]);
                    S[r4*4+3] = fmaf(kv.w, w[s], S[r4*4+3]);
                }
            }
        }

        // ---- P1: vector partials; cache k segment in registers ----
#pragma unroll
        for (int i = 0; i < 8; i++) {
            float pk = 0.f, pq = 0.f;
#pragma unroll
            for (int r4 = 0; r4 < 4; r4++) {
                kr[i][r4] = *(const float4*)&kqsh[0][buf][i][G + r4 * 4];
                float4 qv = *(const float4*)&kqsh[1][buf][i][G + r4 * 4];
                float4 kv = kr[i][r4];
                pk = fmaf(kv.x, S[r4*4+0], pk); pk = fmaf(kv.y, S[r4*4+1], pk);
                pk = fmaf(kv.z, S[r4*4+2], pk); pk = fmaf(kv.w, S[r4*4+3], pk);
                pq = fmaf(qv.x, S[r4*4+0], pq); pq = fmaf(qv.y, S[r4*4+1], pq);
                pq = fmaf(qv.z, S[r4*4+2], pq); pq = fmaf(qv.w, S[r4*4+3], pq);
            }
            pdk[i][j * 9 + g] = pk;
            pdq[i][j * 9 + g] = pq;
        }

        // ---- P1b: exactly the 64 needed pair dots (1 per table slot) ----
        {
            float s0 = 0.f, s1 = 0.f;
            const float* a0 = &kqsh[q0_][buf][si0][G];
            const float* c0 = &kqsh[0][buf][ss0][G];
            const float* a1 = &kqsh[q1_][buf][si1][G];
            const float* c1 = &kqsh[0][buf][ss1][G];
#pragma unroll
            for (int r4 = 0; r4 < 4; r4++) {
                float4 av = *(const float4*)(a0 + r4 * 4);
                float4 cv = *(const float4*)(c0 + r4 * 4);
                s0 = fmaf(av.x, cv.x, s0); s0 = fmaf(av.y, cv.y, s0);
                s0 = fmaf(av.z, cv.z, s0); s0 = fmaf(av.w, cv.w, s0);
                float4 av1 = *(const float4*)(a1 + r4 * 4);
                float4 cv1 = *(const float4*)(c1 + r4 * 4);
                s1 = fmaf(av1.x, cv1.x, s1); s1 = fmaf(av1.y, cv1.y, s1);
                s1 = fmaf(av1.z, cv1.z, s1); s1 = fmaf(av1.w, cv1.w, s1);
            }
            psc[j][g] = s0;
            psc[j + 32][g] = s1;
        }
        __syncthreads();                                   // (B) partials ready

        // ---- distributed reductions ----
        {
            float sa = 0.f, sb2 = 0.f;
#pragma unroll
            for (int gg = 0; gg < 8; gg++) {
                sa  += pdk[g][j * 9 + gg];
                sb2 += pdq[g][j * 9 + gg];
            }
            ar[g][j] = sa;
            br[g][j] = sb2;
            if (tid < 64) {
                float sv = 0.f;
#pragma unroll
                for (int gg = 0; gg < 8; gg++) sv += psc[tid][gg];
                scal[tid] = sv;
            }
        }
        __syncthreads();                                   // (B2) reduced values ready

        // ---- solver warp: triangular solve; writes wsh/E7 for next block's P5 ----
        if (g == 0) {
            float a[8], bq[8];
#pragma unroll
            for (int i = 0; i < 8; i++) { a[i] = ar[i][j]; bq[i] = br[i][j]; }

            float eg[8], bet[8], E[8];
            float Ec = 1.f;
#pragma unroll
            for (int i = 0; i < 8; i++) {
                eg[i]  = egb[buf][0][i];
                bet[i] = egb[buf][1][i];
                Ec *= eg[i];
                E[i] = Ec;
            }

            float dlt[8];
#pragma unroll
            for (int i = 0; i < 8; i++) {
                float acc = vsh[buf][i][j] - E[i] * a[i];
                float rr = 1.f;
#pragma unroll
                for (int s = i - 1; s >= 0; s--) {
                    rr *= eg[s + 1];
                    acc -= rr * scal[TK(i, s)] * dlt[s];
                }
                dlt[i] = bet[i] * acc;
                float oacc = fmaf(E[i], bq[i], scal[TQ(i, i)] * dlt[i]);
                rr = 1.f;
#pragma unroll
                for (int s = i - 1; s >= 0; s--) {
                    rr *= eg[s + 1];
                    oacc = fmaf(rr * scal[TQ(i, s)], dlt[s], oacc);
                }
                o[(size_t)(t0 + i) * VDIM + v_base + j] = oacc;
            }
            float rr = 1.f;
#pragma unroll
            for (int s = 7; s >= 0; s--) {
                wsh[s][j] = rr * dlt[s];
                rr *= eg[s];
            }
            if (j == 0) E7sh = E[7];
        }
        // no barrier: next iteration's barrier (A) orders wsh/E7 before P5
    }
}

// ---------------- RMSNorm * norm_w * SiLU(gate) -> A2 f16 [hi | lo] ----------------
__global__ __launch_bounds__(256) void epilogue_kernel(
    const float* __restrict__ o, const float* __restrict__ proj,
    const float* __restrict__ norm_w, __half* __restrict__ A2)
{
    int t = blockIdx.x, h = blockIdx.y;
    int d = threadIdx.x;
    float x = o[(size_t)t * VDIM + h * DV + d];

    float ss = x * x;
#pragma unroll
    for (int off = 16; off; off >>= 1)
        ss += __shfl_xor_sync(0xffffffffu, ss, off);
    __shared__ float red[8];
    int lane = threadIdx.x & 31, warp = threadIdx.x >> 5;
    if (lane == 0) red[warp] = ss;
    __syncthreads();
    float tot = 0.f;
#pragma unroll
    for (int w = 0; w < 8; w++) tot += red[w];

    float scale = rsqrtf(tot * (1.f / 256.f) + 1e-5f);
    float gg = proj[(size_t)t * PROJN_PAD + 2 * KDIM + VDIM + h * DV + d];
    float silu_g = gg / (1.f + expf(-gg));
    float val = x * scale * norm_w[d] * silu_g;

    __half hi, lo;
    f16split(val, hi, lo);
    __half* row = A2 + (size_t)t * KA2;
    int col = h * DV + d;
    row[col] = hi; row[VDIM + col] = lo;
}

// ---------------- launch ----------------
extern "C" void kernel_launch(void* const* d_in, const int* in_sizes, int n_in,
                              void* d_out, int out_size)
{
    const float* hs      = (const float*)d_in[0];
    const float* Wq      = (const float*)d_in[1];
    const float* Wk      = (const float*)d_in[2];
    const float* Wv      = (const float*)d_in[3];
    const float* Wb      = (const float*)d_in[4];
    const float* Wa      = (const float*)d_in[5];
    const float* Wg      = (const float*)d_in[6];
    const float* Wo      = (const float*)d_in[7];
    const float* conv_wq = (const float*)d_in[8];
    const float* conv_wk = (const float*)d_in[9];
    const float* conv_wv = (const float*)d_in[10];
    const float* A_log   = (const float*)d_in[11];
    const float* dt_bias = (const float*)d_in[12];
    const float* norm_w  = (const float*)d_in[13];
    float* out = (float*)d_out;

    unsigned char* s = nullptr;
    cudaGetSymbolAddress((void**)&s, g_scratch);
    float*   PROJ  = (float*)(s + B_PROJ);
    __half*  A3    = (__half*)(s + B_A3);
    __half*  B3    = (__half*)(s + B_B3);
    __half*  A2    = (__half*)(s + B_A2);
    __half*  B2    = (__half*)(s + B_B2);
    float*   Qb    = (float*)(s + B_Q);
    float*   Kb    = (float*)(s + B_K);
    float*   Vb    = (float*)(s + B_V);
    float*   Ob    = (float*)(s + B_O);
    float*   Gb    = (float*)(s + B_G);
    float*   Bb    = (float*)(s + B_BB);
    float*   Cpart = (float*)(s + B_CP);

    cudaFuncSetAttribute(gemm_f16, cudaFuncAttributeMaxDynamicSharedMemorySize, GEMM_SMEM);

    // 1) merged prep
    prep_all<<<NB_SPLIT + NB_TSP + NB_TSW, 256>>>(hs, Wq, Wk, Wv, Wg, Wb, Wa, Wo, A3, B3, B2);

    // 2) projection GEMM: 128x128 tiles, logical 2P = 64 chunks (P = 32)
    gemm_f16<<<dim3(T_LEN / 128, PROJN_PAD / 128, 1), 256, GEMM_SMEM>>>(
        A3, B3, PROJ, T_LEN, PROJN_PAD, KA1, KB1, 32, 64);

    // 3) fused convs + beta/exp(g)
    conv_fused<<<dim3(T_LEN, NH), 256>>>(PROJ, conv_wq, conv_wk, conv_wv,
                                         A_log, dt_bias, Qb, Kb, Vb, Bb, Gb);

    // 4) scan (256 threads, 3 barriers/block)
    scan_block_kernel<<<NH * 8, 256>>>(Qb, Kb, Vb, Gb, Bb, Ob);

    // 5) epilogue
    epilogue_kernel<<<dim3(T_LEN, NH), 256>>>(Ob, PROJ, norm_w, A2);

    // 6) output GEMM: logical 2P = 96 chunks (P = 48), split-K = 2
    gemm_f16<<<dim3(T_LEN / 128, HID / 128, 2), 256, GEMM_SMEM>>>(
        A2, B2, Cpart, T_LEN, HID, KA2, KB2, 48, 48);
    combine_kernel<<<(T_LEN * HID) / 256, 256>>>(Cpart, out);
}

// round 16
// speedup vs baseline: 1.0758x; 1.0758x over previous
#include <cuda_runtime.h>
#include <cuda_fp16.h>
#include <math.h>
#include <stdint.h>

// ---------------- problem constants ----------------
#define T_LEN 1024
#define HID   2048
#define NH    12
#define DK    128
#define DV    256
#define KDIM  1536
#define VDIM  3072
#define PROJN 9216
#define PROJN_PAD 9344
#define KA1 (2*HID)
#define KB1 (HID)
#define KA2 (2*VDIM)
#define KB2 (VDIM)

// ---------------- scratch ----------------
constexpr size_t SZ_PROJ = (size_t)T_LEN * PROJN_PAD * 4;
constexpr size_t SZ_A3   = (size_t)T_LEN * KA1 * 2;
constexpr size_t SZ_B3   = (size_t)PROJN_PAD * KB1 * 2;
constexpr size_t SZ_A2   = (size_t)T_LEN * KA2 * 2;
constexpr size_t SZ_B2   = (size_t)HID * KB2 * 2;
constexpr size_t SZ_QK   = (size_t)T_LEN * KDIM * 4;
constexpr size_t SZ_V    = (size_t)T_LEN * VDIM * 4;
constexpr size_t SZ_H    = (size_t)T_LEN * NH * 4;
constexpr size_t SZ_CP   = (size_t)3 * T_LEN * HID * 4;

constexpr size_t B_PROJ = 0;
constexpr size_t B_A3   = B_PROJ + SZ_PROJ;
constexpr size_t B_B3   = B_A3 + SZ_A3;
constexpr size_t B_A2   = B_B3 + SZ_B3;
constexpr size_t B_B2   = B_A2 + SZ_A2;
constexpr size_t B_Q    = B_B2 + SZ_B2;
constexpr size_t B_K    = B_Q + SZ_QK;
constexpr size_t B_V    = B_K + SZ_QK;
constexpr size_t B_O    = B_V + SZ_V;
constexpr size_t B_G    = B_O + SZ_V;
constexpr size_t B_BB   = B_G + SZ_H;
constexpr size_t B_CP   = B_BB + SZ_H;
constexpr size_t SCRATCH_BYTES = B_CP + SZ_CP;

__device__ __align__(256) unsigned char g_scratch[SCRATCH_BYTES];

// pair table: slot<28 -> K pair (si,ss), s<i ; slot>=28 -> Q pair (si,ss), s<=i
// enc = (isQ<<6) | (si<<3) | ss
__constant__ unsigned char PAIR_TAB[64] = {
    0x08,
    0x10,0x11,
    0x18,0x19,0x1a,
    0x20,0x21,0x22,0x23,
    0x28,0x29,0x2a,0x2b,0x2c,
    0x30,0x31,0x32,0x33,0x34,0x35,
    0x38,0x39,0x3a,0x3b,0x3c,0x3d,0x3e,
    0x40,
    0x48,0x49,
    0x50,0x51,0x52,
    0x58,0x59,0x5a,0x5b,
    0x60,0x61,0x62,0x63,0x64,
    0x68,0x69,0x6a,0x6b,0x6c,0x6d,
    0x70,0x71,0x72,0x73,0x74,0x75,0x76,
    0x78,0x79,0x7a,0x7b,0x7c,0x7d,0x7e,0x7f
};
#define TK(i,s) ((i)*((i)-1)/2 + (s))
#define TQ(i,s) (28 + (i)*((i)+1)/2 + (s))

// ---------------- PTX helpers ----------------
__device__ __forceinline__ uint32_t smem_u32(const void* p) {
    uint32_t a;
    asm("{ .reg .u64 t; cvta.to.shared.u64 t, %1; cvt.u32.u64 %0, t; }" : "=r"(a) : "l"(p));
    return a;
}
__device__ __forceinline__ void cpasync16(uint32_t dst, const void* src) {
    asm volatile("cp.async.cg.shared.global [%0], [%1], 16;" :: "r"(dst), "l"(src) : "memory");
}
#define CP_COMMIT() asm volatile("cp.async.commit_group;" ::: "memory")
#define CP_WAIT0()  asm volatile("cp.async.wait_group 0;" ::: "memory")
#define CP_WAIT1()  asm volatile("cp.async.wait_group 1;" ::: "memory")

__device__ __forceinline__ void ldm4(uint32_t* r, uint32_t addr) {
    asm volatile("ldmatrix.sync.aligned.m8n8.x4.shared.b16 {%0,%1,%2,%3}, [%4];"
        : "=r"(r[0]), "=r"(r[1]), "=r"(r[2]), "=r"(r[3]) : "r"(addr));
}
__device__ __forceinline__ void mma16816(float* c, const uint32_t* a, uint32_t b0, uint32_t b1) {
    asm volatile("mma.sync.aligned.m16n8k16.row.col.f32.f16.f16.f32 "
        "{%0,%1,%2,%3}, {%4,%5,%6,%7}, {%8,%9}, {%0,%1,%2,%3};"
        : "+f"(c[0]), "+f"(c[1]), "+f"(c[2]), "+f"(c[3])
        : "r"(a[0]), "r"(a[1]), "r"(a[2]), "r"(a[3]), "r"(b0), "r"(b1));
}
#define SWZ128(o) ((o) ^ (((o) >> 3) & 0x70))

// ---------------- fp16 mma.sync GEMM (proven R10 config): CTA 128x128, 3-stage ----------------
#define GEMM_SMEM 98304

__global__ __launch_bounds__(256, 2) void gemm_f16(
    const __half* __restrict__ A, const __half* __restrict__ Bt,
    float* __restrict__ C, int M, int N, int KA, int KB, int P, int chunksPerZ)
{
    extern __shared__ unsigned char smem_raw[];
    uint32_t sb = smem_u32(smem_raw);

    const int tid  = threadIdx.x;
    const int wid  = tid >> 5;
    const int lane = tid & 31;
    const int wm   = wid & 3;
    const int wn   = wid >> 2;

    const int bm = blockIdx.x * 128;
    const int bn = blockIdx.y * 128;
    const int gcBase = blockIdx.z * chunksPerZ;
    float* Cz = C + (size_t)blockIdx.z * M * N;

    const int lrow = tid >> 1;
    const int lcolB = (tid & 1) * 64;
    const __half* Arow = A + (size_t)(bm + lrow) * KA;
    const __half* Brow = Bt + (size_t)(bn + lrow) * KB;
    uint32_t st[4];
#pragma unroll
    for (int j = 0; j < 4; j++) {
        uint32_t o = (uint32_t)lrow * 128u + (uint32_t)lcolB + j * 16u;
        st[j] = SWZ128(o);
    }

    const int l8 = lane & 7;
    const int rowA = wm * 32 + ((lane >> 3) & 1) * 8 + l8;
    const uint32_t colA = (uint32_t)((lane >> 4) * 16);
    const uint32_t xorA = (uint32_t)((rowA & 7) << 4);
    const int rowB = wn * 64 + ((lane >> 4) & 1) * 8 + l8;
    const uint32_t colB = (uint32_t)(((lane >> 3) & 1) * 16);
    const uint32_t xorB = (uint32_t)((rowB & 7) << 4);

    float c[2][8][4];
#pragma unroll
    for (int mf = 0; mf < 2; mf++)
#pragma unroll
        for (int nf = 0; nf < 8; nf++)
#pragma unroll
            for (int i = 0; i < 4; i++) c[mf][nf][i] = 0.f;

    auto issue = [&](int gc, int s) {
        int bc = (gc < P) ? gc : gc - P;
        const unsigned char* Ag = (const unsigned char*)(Arow + gc * 64);
        const unsigned char* Bg = (const unsigned char*)(Brow + bc * 64);
        uint32_t ab = sb + (uint32_t)s * 32768u;
        uint32_t bb = ab + 16384u;
#pragma unroll
        for (int j = 0; j < 4; j++) cpasync16(ab + st[j], Ag + lcolB + j * 16);
#pragma unroll
        for (int j = 0; j < 4; j++) cpasync16(bb + st[j], Bg + lcolB + j * 16);
    };

#pragma unroll
    for (int p = 0; p < 2; p++) {
        issue(gcBase + p, p);
        CP_COMMIT();
    }

    int sc = 0;
    int sp = 2;

    for (int i = 0; i < chunksPerZ; i++) {
        CP_WAIT1();
        __syncthreads();

        if (i + 2 < chunksPerZ) issue(gcBase + i + 2, sp);
        CP_COMMIT();

        uint32_t ab = sb + (uint32_t)sc * 32768u;
        uint32_t bb = ab + 16384u;
#pragma unroll
        for (int ks = 0; ks < 4; ks++) {
            uint32_t af0[4], af1[4];
            uint32_t ac = ((uint32_t)(ks * 32) + colA) ^ xorA;
            ldm4(af0, ab + (uint32_t)rowA * 128u + ac);
            ldm4(af1, ab + (uint32_t)rowA * 128u + 2048u + ac);

            uint32_t bf[4][4];
            uint32_t bc = ((uint32_t)(ks * 32) + colB) ^ xorB;
#pragma unroll
            for (int p = 0; p < 4; p++)
                ldm4(bf[p], bb + (uint32_t)(rowB + p * 16) * 128u + bc);

#pragma unroll
            for (int nf = 0; nf < 8; nf++) {
                uint32_t b0 = bf[nf >> 1][(nf & 1) * 2 + 0];
                uint32_t b1 = bf[nf >> 1][(nf & 1) * 2 + 1];
                mma16816(c[0][nf], af0, b0, b1);
                mma16816(c[1][nf], af1, b0, b1);
            }
        }

        sc = (sc == 2) ? 0 : sc + 1;
        sp = (sp == 2) ? 0 : sp + 1;
    }

    const int g  = lane >> 2;
    const int t4 = lane & 3;
#pragma unroll
    for (int mf = 0; mf < 2; mf++) {
#pragma unroll
        for (int nf = 0; nf < 8; nf++) {
            int row = bm + wm * 32 + mf * 16 + g;
            int col = bn + wn * 64 + nf * 8 + t4 * 2;
            *(float2*)(Cz + (size_t)row * N + col)       = make_float2(c[mf][nf][0], c[mf][nf][1]);
            *(float2*)(Cz + (size_t)(row + 8) * N + col) = make_float2(c[mf][nf][2], c[mf][nf][3]);
        }
    }
}

__global__ __launch_bounds__(256) void combine_kernel(const float* __restrict__ c012, float* __restrict__ out)
{
    int i = blockIdx.x * 256 + threadIdx.x;
    const size_t S = (size_t)T_LEN * HID;
    out[i] = c012[i] + c012[i + S] + c012[i + 2 * S];
}

// ---------------- fp16 hi/lo split ----------------
__device__ __forceinline__ void f16split(float x, __half& hi, __half& lo) {
    hi = __float2half_rn(x);
    lo = __float2half_rn(x - __half2float(hi));
}

// ---------------- merged prep kernel ----------------
#define NB_SPLIT 2048
#define NB_TSP   ((HID/64)*(PROJN_PAD/32))
#define NB_TSW   ((VDIM/64)*(HID/32))

__device__ void split_hs_body(const float* __restrict__ hs, __half* __restrict__ A3, int b)
{
    int idx = b * 256 + threadIdx.x;
    int t = idx >> 9;
    int kq = (idx & 511) * 4;
    float4 x = *(const float4*)(hs + (size_t)t * HID + kq);
    __half2 h01, h23, l01, l23;
    __half h, l;
    f16split(x.x, h, l); h01.x = h; l01.x = l;
    f16split(x.y, h, l); h01.y = h; l01.y = l;
    f16split(x.z, h, l); h23.x = h; l23.x = l;
    f16split(x.w, h, l); h23.y = h; l23.y = l;
    __half* row = A3 + (size_t)t * KA1;
    *(__half2*)(row + kq)           = h01;
    *(__half2*)(row + kq + 2)       = h23;
    *(__half2*)(row + HID + kq)     = l01;
    *(__half2*)(row + HID + kq + 2) = l23;
}

template<int KW>
__device__ __forceinline__ void tstore_tile(
    const float* tileflat, int k0, int n0, __half* Bout)
{
    const float (*tile)[72] = (const float (*)[72])tileflat;
    int tid = threadIdx.x;
#pragma unroll
    for (int pass = 0; pass < 4; pass++) {
        int nl = (tid >> 5) + pass * 8;
        int kl = (tid & 31) * 2;
        __half2 hp;
        hp.x = __float2half_rn(tile[nl][kl]);
        hp.y = __float2half_rn(tile[nl][kl + 1]);
        *reinterpret_cast<__half2*>(Bout + (size_t)(n0 + nl) * KW + k0 + kl) = hp;
    }
}

__device__ void tsplit_proj_body(
    const float* __restrict__ Wq, const float* __restrict__ Wk,
    const float* __restrict__ Wv, const float* __restrict__ Wg,
    const float* __restrict__ Wb, const float* __restrict__ Wa,
    __half* __restrict__ B3, int bx, int by)
{
    __shared__ float tile[32][72];
    int k0 = bx * 64, n0 = by * 32;
    int tid = threadIdx.x;
    int nl = tid & 31, n = n0 + nl;
#pragma unroll
    for (int i = 0; i < 8; i++) {
        int k = k0 + (tid >> 5) + i * 8;
        float v;
        if      (n < KDIM)            v = Wq[(size_t)k * KDIM + n];
        else if (n < 2 * KDIM)        v = Wk[(size_t)k * KDIM + n - KDIM];
        else if (n < 2 * KDIM + VDIM) v = Wv[(size_t)k * VDIM + n - 2 * KDIM];
        else if (n < PROJN)           v = Wg[(size_t)k * VDIM + n - 2 * KDIM - VDIM];
        else if (n < PROJN + NH)      v = Wb[(size_t)k * NH + n - PROJN];
        else if (n < PROJN + 2 * NH)  v = Wa[(size_t)k * NH + n - PROJN - NH];
        else                          v = 0.f;
        tile[nl][(tid >> 5) + i * 8] = v;
    }
    __syncthreads();
    tstore_tile<KB1>(&tile[0][0], k0, n0, B3);
}

__device__ void tsplit_wo_body(const float* __restrict__ Wo, __half* __restrict__ B2, int bx, int by)
{
    __shared__ float tile[32][72];
    int k0 = bx * 64, n0 = by * 32;
    int tid = threadIdx.x;
    int nl = tid & 31;
#pragma unroll
    for (int i = 0; i < 8; i++) {
        int k = k0 + (tid >> 5) + i * 8;
        tile[nl][(tid >> 5) + i * 8] = Wo[(size_t)k * HID + n0 + nl];
    }
    __syncthreads();
    tstore_tile<KB2>(&tile[0][0], k0, n0, B2);
}

__global__ __launch_bounds__(256) void prep_all(
    const float* __restrict__ hs,
    const float* __restrict__ Wq, const float* __restrict__ Wk,
    const float* __restrict__ Wv, const float* __restrict__ Wg,
    const float* __restrict__ Wb, const float* __restrict__ Wa,
    const float* __restrict__ Wo,
    __half* __restrict__ A3, __half* __restrict__ B3, __half* __restrict__ B2)
{
    int b = blockIdx.x;
    if (b < NB_SPLIT) {
        split_hs_body(hs, A3, b);
    } else if (b < NB_SPLIT + NB_TSP) {
        int bb = b - NB_SPLIT;
        tsplit_proj_body(Wq, Wk, Wv, Wg, Wb, Wa, B3, bb % (HID / 64), bb / (HID / 64));
    } else {
        int bb = b - NB_SPLIT - NB_TSP;
        tsplit_wo_body(Wo, B2, bb % (VDIM / 64), bb / (VDIM / 64));
    }
}

// ---------------- fused conv (+ beta/g fold on h==0 blocks) ----------------
__global__ __launch_bounds__(256) void conv_fused(
    const float* __restrict__ proj,
    const float* __restrict__ wq, const float* __restrict__ wk, const float* __restrict__ wv,
    const float* __restrict__ A_log, const float* __restrict__ dt_bias,
    float* __restrict__ qo, float* __restrict__ ko, float* __restrict__ vo,
    float* __restrict__ beta, float* __restrict__ egout)
{
    int t = blockIdx.x, h = blockIdx.y;
    int d = threadIdx.x;
    int which = d >> 7;
    int dd = d & 127;
    int ch = h * DK + dd;

    const float* w = which ? wk : wq;
    int cqk = (which ? KDIM : 0) + ch;
    int cv  = 2 * KDIM + h * DV + d;

    float y = 0.f, yv = 0.f;
#pragma unroll
    for (int i = 0; i < 4; i++) {
        int tt = t - 3 + i;
        if (tt >= 0) {
            const float* prow = proj + (size_t)tt * PROJN_PAD;
            y  = fmaf(prow[cqk], w[ch * 4 + i], y);
            yv = fmaf(prow[cv], wv[(h * DV + d) * 4 + i], yv);
        }
    }
    y  = y / (1.f + expf(-y));
    yv = yv / (1.f + expf(-yv));

    float ss = y * y;
#pragma unroll
    for (int off = 16; off; off >>= 1)
        ss += __shfl_xor_sync(0xffffffffu, ss, off);
    __shared__ float red[8];
    int lane = d & 31, warp = d >> 5;
    if (lane == 0) red[warp] = ss;
    __syncthreads();
    float tot = red[which * 4 + 0] + red[which * 4 + 1] + red[which * 4 + 2] + red[which * 4 + 3];

    float* dst = which ? ko : qo;
    dst[(size_t)t * KDIM + ch] = y * rsqrtf(tot + 1e-6f);
    vo[(size_t)t * VDIM + h * DV + d] = yv;

    if (h == 0 && d < 24) {
        float sv = proj[(size_t)t * PROJN_PAD + PROJN + d];
        if (d < NH) {
            beta[t * NH + d] = 1.f / (1.f + expf(-sv));
        } else {
            int hh = d - NH;
            float x = sv + dt_bias[hh];
            float sp = (x > 20.f) ? x : log1pf(expf(x));
            egout[t * NH + hh] = expf(-expf(A_log[hh]) * sp);
        }
    }
}

// ---------------- block-processed gated delta-rule scan (B=8), v6 ----------------
// R13 structure (4 barriers, distributed reductions) plus:
//   - k/q rows padded to 132 floats (kills P1b 8-way bank conflicts)
//   - triangular pair set: 64 dots instead of 128
//   - solver computes only the serial dlt chain; o computed by all 8 warps after C
#define KQPAD 132
#define NBLK 128

__global__ __launch_bounds__(256, 1) void scan_block_kernel(
    const float* __restrict__ q, const float* __restrict__ k,
    const float* __restrict__ v, const float* __restrict__ eg_in,
    const float* __restrict__ bb, float* __restrict__ o)
{
    const int h = blockIdx.x >> 3;
    const int chunk = blockIdx.x & 7;
    const int tid = threadIdx.x;
    const int j = tid & 31;
    const int g = tid >> 5;
    const int G = g * 16;

    __shared__ float kqsh[2][2][8][KQPAD];   // [0=k,1=q][buf][step][dim(128)+pad]
    __shared__ float vsh[2][8][32];
    __shared__ float egb[2][2][8];
    __shared__ float pdk[8][32 * 9];
    __shared__ float pdq[8][32 * 9];
    __shared__ float psc[64][9];
    __shared__ float ar[8][33], br[8][33];
    __shared__ float scal[64];
    __shared__ float dltsh[8][32];
    __shared__ float wsh[8][32];
    __shared__ float E7sh;

    float S[16];
#pragma unroll
    for (int i = 0; i < 16; i++) S[i] = 0.f;
    float4 kr[8][4];

    const int kq_base = h * DK;
    const int v_base  = h * DV + chunk * 32;

    const int ki  = tid >> 5;
    const int kf  = (tid & 31) * 4;
    const int vi  = tid >> 3;
    const int vf  = (tid & 7) * 4;
    uint32_t kdst[2], qdst[2], vdst[2];
#pragma unroll
    for (int p = 0; p < 2; p++) {
        kdst[p] = smem_u32(&kqsh[0][p][ki][kf]);
        qdst[p] = smem_u32(&kqsh[1][p][ki][kf]);
        vdst[p] = smem_u32(&vsh[p][0][0]) + (uint32_t)(vi * 32 + vf) * 4u;
    }

    const int eb_i = tid - 192;
    float pebs = 0.f;
    if (eb_i >= 0 && eb_i < 16) {
        int i0 = eb_i & 7;
        pebs = (eb_i < 8) ? eg_in[(size_t)i0 * NH + h] : bb[(size_t)i0 * NH + h];
    }

    // decode my two pair-table entries (loop-invariant)
    const unsigned e0 = PAIR_TAB[j];
    const unsigned e1 = PAIR_TAB[j + 32];
    const int q0_ = e0 >> 6, si0 = (e0 >> 3) & 7, ss0 = e0 & 7;
    const int q1_ = e1 >> 6, si1 = (e1 >> 3) & 7, ss1 = e1 & 7;

    {
        cpasync16(kdst[0], k + (size_t)ki * KDIM + kq_base + kf);
        cpasync16(qdst[0], q + (size_t)ki * KDIM + kq_base + kf);
        if (tid < 64) cpasync16(vdst[0], v + (size_t)vi * VDIM + v_base + vf);
        CP_COMMIT();
    }

    for (int b = 0; b < NBLK; b++) {
        const int buf = b & 1;
        const int t0 = b * 8;

        CP_WAIT0();
        if (eb_i >= 0 && eb_i < 16)
            egb[buf][eb_i >> 3][eb_i & 7] = pebs;
        __syncthreads();                                   // (A)

        if (b + 1 < NBLK) {
            const int nb = (b + 1) & 1;
            const size_t r0 = (size_t)(t0 + 8);
            cpasync16(kdst[nb], k + (r0 + ki) * KDIM + kq_base + kf);
            cpasync16(qdst[nb], q + (r0 + ki) * KDIM + kq_base + kf);
            if (tid < 64) cpasync16(vdst[nb], v + (r0 + vi) * VDIM + v_base + vf);
            if (eb_i >= 0 && eb_i < 16) {
                int i0 = eb_i & 7;
                pebs = (eb_i < 8) ? eg_in[(r0 + i0) * NH + h] : bb[(r0 + i0) * NH + h];
            }
            CP_COMMIT();
        }

        // ---- P1: vector partials; cache k segment in registers ----
#pragma unroll
        for (int i = 0; i < 8; i++) {
            float pk = 0.f, pq = 0.f;
#pragma unroll
            for (int r4 = 0; r4 < 4; r4++) {
                kr[i][r4] = *(const float4*)&kqsh[0][buf][i][G + r4 * 4];
                float4 qv = *(const float4*)&kqsh[1][buf][i][G + r4 * 4];
                float4 kv = kr[i][r4];
                pk = fmaf(kv.x, S[r4*4+0], pk); pk = fmaf(kv.y, S[r4*4+1], pk);
                pk = fmaf(kv.z, S[r4*4+2], pk); pk = fmaf(kv.w, S[r4*4+3], pk);
                pq = fmaf(qv.x, S[r4*4+0], pq); pq = fmaf(qv.y, S[r4*4+1], pq);
                pq = fmaf(qv.z, S[r4*4+2], pq); pq = fmaf(qv.w, S[r4*4+3], pq);
            }
            pdk[i][j * 9 + g] = pk;
            pdq[i][j * 9 + g] = pq;
        }

        // ---- P1b: 64 triangular pair dots, conflict-free thanks to KQPAD ----
        {
            float s0 = 0.f, s1 = 0.f;
            const float* a0 = &kqsh[q0_][buf][si0][G];
            const float* c0 = &kqsh[0][buf][ss0][G];
            const float* a1 = &kqsh[q1_][buf][si1][G];
            const float* c1 = &kqsh[0][buf][ss1][G];
#pragma unroll
            for (int r4 = 0; r4 < 4; r4++) {
                float4 av = *(const float4*)(a0 + r4 * 4);
                float4 cv = *(const float4*)(c0 + r4 * 4);
                s0 = fmaf(av.x, cv.x, s0); s0 = fmaf(av.y, cv.y, s0);
                s0 = fmaf(av.z, cv.z, s0); s0 = fmaf(av.w, cv.w, s0);
                float4 av1 = *(const float4*)(a1 + r4 * 4);
                float4 cv1 = *(const float4*)(c1 + r4 * 4);
                s1 = fmaf(av1.x, cv1.x, s1); s1 = fmaf(av1.y, cv1.y, s1);
                s1 = fmaf(av1.z, cv1.z, s1); s1 = fmaf(av1.w, cv1.w, s1);
            }
            psc[j][g] = s0;
            psc[j + 32][g] = s1;
        }
        __syncthreads();                                   // (B)

        // ---- distributed reductions ----
        {
            float sa = 0.f, sb2 = 0.f;
#pragma unroll
            for (int gg = 0; gg < 8; gg++) {
                sa  += pdk[g][j * 9 + gg];
                sb2 += pdq[g][j * 9 + gg];
            }
            ar[g][j] = sa;
            br[g][j] = sb2;
            if (tid < 64) {
                float sv = 0.f;
#pragma unroll
                for (int gg = 0; gg < 8; gg++) sv += psc[tid][gg];
                scal[tid] = sv;
            }
        }
        __syncthreads();                                   // (B2)

        // ---- solver warp: dlt chain only ----
        if (g == 0) {
            float eg[8], bet[8], E[8];
            float Ec = 1.f;
#pragma unroll
            for (int i = 0; i < 8; i++) {
                eg[i]  = egb[buf][0][i];
                bet[i] = egb[buf][1][i];
                Ec *= eg[i];
                E[i] = Ec;
            }
            float dlt[8];
#pragma unroll
            for (int i = 0; i < 8; i++) {
                float acc = vsh[buf][i][j] - E[i] * ar[i][j];
                float rr = 1.f;
#pragma unroll
                for (int s = i - 1; s >= 0; s--) {
                    rr *= eg[s + 1];
                    acc -= rr * scal[TK(i, s)] * dlt[s];
                }
                dlt[i] = bet[i] * acc;
                dltsh[i][j] = dlt[i];
            }
            float rr = 1.f;
#pragma unroll
            for (int s = 7; s >= 0; s--) {
                wsh[s][j] = rr * dlt[s];
                rr *= eg[s];
            }
            if (j == 0) E7sh = E[7];
        }
        __syncthreads();                                   // (C)

        // ---- distributed o: warp g computes step i=g for all 32 columns ----
        {
            const int i = g;
            float eg[8];
#pragma unroll
            for (int s = 0; s < 8; s++) eg[s] = egb[buf][0][s];
            float E = 1.f;
#pragma unroll
            for (int s = 0; s < 8; s++) if (s <= i) E *= eg[s];
            float oacc = fmaf(E, br[i][j], scal[TQ(i, i)] * dltsh[i][j]);
            float rr = 1.f;
#pragma unroll
            for (int s = 6; s >= 0; s--) {
                if (s < i) {
                    rr *= eg[s + 1];
                    oacc = fmaf(rr * scal[TQ(i, s)], dltsh[s][j], oacc);
                }
            }
            o[(size_t)(t0 + i) * VDIM + v_base + j] = oacc;
        }

        // ---- P5: rank-8 state update from register-cached k ----
        float E7 = E7sh;
        float w[8];
#pragma unroll
        for (int s = 0; s < 8; s++) w[s] = wsh[s][j];
#pragma unroll
        for (int r = 0; r < 16; r++) S[r] *= E7;
#pragma unroll
        for (int s = 0; s < 8; s++) {
#pragma unroll
            for (int r4 = 0; r4 < 4; r4++) {
                float4 kv = kr[s][r4];
                S[r4*4+0] = fmaf(kv.x, w[s], S[r4*4+0]);
                S[r4*4+1] = fmaf(kv.y, w[s], S[r4*4+1]);
                S[r4*4+2] = fmaf(kv.z, w[s], S[r4*4+2]);
                S[r4*4+3] = fmaf(kv.w, w[s], S[r4*4+3]);
            }
        }
        // barrier (A) of next block orders wsh/dltsh reads vs next solver writes
        __syncthreads();                                   // (D) protect smem reuse
    }
}

// ---------------- RMSNorm * norm_w * SiLU(gate) -> A2 f16 [hi | lo] ----------------
__global__ __launch_bounds__(256) void epilogue_kernel(
    const float* __restrict__ o, const float* __restrict__ proj,
    const float* __restrict__ norm_w, __half* __restrict__ A2)
{
    int t = blockIdx.x, h = blockIdx.y;
    int d = threadIdx.x;
    float x = o[(size_t)t * VDIM + h * DV + d];

    float ss = x * x;
#pragma unroll
    for (int off = 16; off; off >>= 1)
        ss += __shfl_xor_sync(0xffffffffu, ss, off);
    __shared__ float red[8];
    int lane = threadIdx.x & 31, warp = threadIdx.x >> 5;
    if (lane == 0) red[warp] = ss;
    __syncthreads();
    float tot = 0.f;
#pragma unroll
    for (int w = 0; w < 8; w++) tot += red[w];

    float scale = rsqrtf(tot * (1.f / 256.f) + 1e-5f);
    float gg = proj[(size_t)t * PROJN_PAD + 2 * KDIM + VDIM + h * DV + d];
    float silu_g = gg / (1.f + expf(-gg));
    float val = x * scale * norm_w[d] * silu_g;

    __half hi, lo;
    f16split(val, hi, lo);
    __half* row = A2 + (size_t)t * KA2;
    int col = h * DV + d;
    row[col] = hi; row[VDIM + col] = lo;
}

// ---------------- launch ----------------
extern "C" void kernel_launch(void* const* d_in, const int* in_sizes, int n_in,
                              void* d_out, int out_size)
{
    const float* hs      = (const float*)d_in[0];
    const float* Wq      = (const float*)d_in[1];
    const float* Wk      = (const float*)d_in[2];
    const float* Wv      = (const float*)d_in[3];
    const float* Wb      = (const float*)d_in[4];
    const float* Wa      = (const float*)d_in[5];
    const float* Wg      = (const float*)d_in[6];
    const float* Wo      = (const float*)d_in[7];
    const float* conv_wq = (const float*)d_in[8];
    const float* conv_wk = (const float*)d_in[9];
    const float* conv_wv = (const float*)d_in[10];
    const float* A_log   = (const float*)d_in[11];
    const float* dt_bias = (const float*)d_in[12];
    const float* norm_w  = (const float*)d_in[13];
    float* out = (float*)d_out;

    unsigned char* s = nullptr;
    cudaGetSymbolAddress((void**)&s, g_scratch);
    float*   PROJ  = (float*)(s + B_PROJ);
    __half*  A3    = (__half*)(s + B_A3);
    __half*  B3    = (__half*)(s + B_B3);
    __half*  A2    = (__half*)(s + B_A2);
    __half*  B2    = (__half*)(s + B_B2);
    float*   Qb    = (float*)(s + B_Q);
    float*   Kb    = (float*)(s + B_K);
    float*   Vb    = (float*)(s + B_V);
    float*   Ob    = (float*)(s + B_O);
    float*   Gb    = (float*)(s + B_G);
    float*   Bb    = (float*)(s + B_BB);
    float*   Cpart = (float*)(s + B_CP);

    cudaFuncSetAttribute(gemm_f16, cudaFuncAttributeMaxDynamicSharedMemorySize, GEMM_SMEM);

    // 1) merged prep
    prep_all<<<NB_SPLIT + NB_TSP + NB_TSW, 256>>>(hs, Wq, Wk, Wv, Wg, Wb, Wa, Wo, A3, B3, B2);

    // 2) projection GEMM: 128x128 tiles, logical 2P = 64 chunks (P = 32)
    gemm_f16<<<dim3(T_LEN / 128, PROJN_PAD / 128, 1), 256, GEMM_SMEM>>>(
        A3, B3, PROJ, T_LEN, PROJN_PAD, KA1, KB1, 32, 64);

    // 3) fused convs + beta/exp(g)
    conv_fused<<<dim3(T_LEN, NH), 256>>>(PROJ, conv_wq, conv_wk, conv_wv,
                                         A_log, dt_bias, Qb, Kb, Vb, Bb, Gb);

    // 4) scan
    scan_block_kernel<<<NH * 8, 256>>>(Qb, Kb, Vb, Gb, Bb, Ob);

    // 5) epilogue
    epilogue_kernel<<<dim3(T_LEN, NH), 256>>>(Ob, PROJ, norm_w, A2);

    // 6) output GEMM: logical 2P = 96 chunks (P = 48), split-K = 3 (32 chunks each)
    gemm_f16<<<dim3(T_LEN / 128, HID / 128, 3), 256, GEMM_SMEM>>>(
        A2, B2, Cpart, T_LEN, HID, KA2, KB2, 48, 32);
    combine_kernel<<<(T_LEN * HID) / 256, 256>>>(Cpart, out);
}

// round 17
// speedup vs baseline: 1.1304x; 1.0507x over previous
#include <cuda_runtime.h>
#include <cuda_fp16.h>
#include <math.h>
#include <stdint.h>

// ---------------- problem constants ----------------
#define T_LEN 1024
#define HID   2048
#define NH    12
#define DK    128
#define DV    256
#define KDIM  1536
#define VDIM  3072
#define PROJN 9216
#define PROJN_PAD 9344
#define KA1 (2*HID)
#define KB1 (HID)
#define KA2 (2*VDIM)
#define KB2 (VDIM)

// ---------------- scratch ----------------
constexpr size_t SZ_PROJ = (size_t)T_LEN * PROJN_PAD * 4;
constexpr size_t SZ_A3   = (size_t)T_LEN * KA1 * 2;
constexpr size_t SZ_B3   = (size_t)PROJN_PAD * KB1 * 2;
constexpr size_t SZ_A2   = (size_t)T_LEN * KA2 * 2;
constexpr size_t SZ_B2   = (size_t)HID * KB2 * 2;
constexpr size_t SZ_QK   = (size_t)T_LEN * KDIM * 4;
constexpr size_t SZ_V    = (size_t)T_LEN * VDIM * 4;
constexpr size_t SZ_H    = (size_t)T_LEN * NH * 4;
constexpr size_t SZ_CP   = (size_t)3 * T_LEN * HID * 4;

constexpr size_t B_PROJ = 0;
constexpr size_t B_A3   = B_PROJ + SZ_PROJ;
constexpr size_t B_B3   = B_A3 + SZ_A3;
constexpr size_t B_A2   = B_B3 + SZ_B3;
constexpr size_t B_B2   = B_A2 + SZ_A2;
constexpr size_t B_Q    = B_B2 + SZ_B2;
constexpr size_t B_K    = B_Q + SZ_QK;
constexpr size_t B_V    = B_K + SZ_QK;
constexpr size_t B_O    = B_V + SZ_V;
constexpr size_t B_G    = B_O + SZ_V;
constexpr size_t B_BB   = B_G + SZ_H;
constexpr size_t B_CP   = B_BB + SZ_H;
constexpr size_t SCRATCH_BYTES = B_CP + SZ_CP;

__device__ __align__(256) unsigned char g_scratch[SCRATCH_BYTES];

// pair table: slot<28 -> K pair (si,ss), s<i ; slot>=28 -> Q pair (si,ss), s<=i
// enc = (isQ<<6) | (si<<3) | ss
__constant__ unsigned char PAIR_TAB[64] = {
    0x08,
    0x10,0x11,
    0x18,0x19,0x1a,
    0x20,0x21,0x22,0x23,
    0x28,0x29,0x2a,0x2b,0x2c,
    0x30,0x31,0x32,0x33,0x34,0x35,
    0x38,0x39,0x3a,0x3b,0x3c,0x3d,0x3e,
    0x40,
    0x48,0x49,
    0x50,0x51,0x52,
    0x58,0x59,0x5a,0x5b,
    0x60,0x61,0x62,0x63,0x64,
    0x68,0x69,0x6a,0x6b,0x6c,0x6d,
    0x70,0x71,0x72,0x73,0x74,0x75,0x76,
    0x78,0x79,0x7a,0x7b,0x7c,0x7d,0x7e,0x7f
};
#define TK(i,s) ((i)*((i)-1)/2 + (s))
#define TQ(i,s) (28 + (i)*((i)+1)/2 + (s))

// ---------------- PTX helpers ----------------
__device__ __forceinline__ uint32_t smem_u32(const void* p) {
    uint32_t a;
    asm("{ .reg .u64 t; cvta.to.shared.u64 t, %1; cvt.u32.u64 %0, t; }" : "=r"(a) : "l"(p));
    return a;
}
__device__ __forceinline__ void cpasync16(uint32_t dst, const void* src) {
    asm volatile("cp.async.cg.shared.global [%0], [%1], 16;" :: "r"(dst), "l"(src) : "memory");
}
#define CP_COMMIT() asm volatile("cp.async.commit_group;" ::: "memory")
#define CP_WAIT0()  asm volatile("cp.async.wait_group 0;" ::: "memory")
#define CP_WAIT1()  asm volatile("cp.async.wait_group 1;" ::: "memory")

__device__ __forceinline__ void ldm4(uint32_t* r, uint32_t addr) {
    asm volatile("ldmatrix.sync.aligned.m8n8.x4.shared.b16 {%0,%1,%2,%3}, [%4];"
        : "=r"(r[0]), "=r"(r[1]), "=r"(r[2]), "=r"(r[3]) : "r"(addr));
}
__device__ __forceinline__ void mma16816(float* c, const uint32_t* a, uint32_t b0, uint32_t b1) {
    asm volatile("mma.sync.aligned.m16n8k16.row.col.f32.f16.f16.f32 "
        "{%0,%1,%2,%3}, {%4,%5,%6,%7}, {%8,%9}, {%0,%1,%2,%3};"
        : "+f"(c[0]), "+f"(c[1]), "+f"(c[2]), "+f"(c[3])
        : "r"(a[0]), "r"(a[1]), "r"(a[2]), "r"(a[3]), "r"(b0), "r"(b1));
}
#define SWZ128(o) ((o) ^ (((o) >> 3) & 0x70))

// ---------------- fp16 mma.sync GEMM (proven R10 config): CTA 128x128, 3-stage ----------------
#define GEMM_SMEM 98304

__global__ __launch_bounds__(256, 2) void gemm_f16(
    const __half* __restrict__ A, const __half* __restrict__ Bt,
    float* __restrict__ C, int M, int N, int KA, int KB, int P, int chunksPerZ)
{
    extern __shared__ unsigned char smem_raw[];
    uint32_t sb = smem_u32(smem_raw);

    const int tid  = threadIdx.x;
    const int wid  = tid >> 5;
    const int lane = tid & 31;
    const int wm   = wid & 3;
    const int wn   = wid >> 2;

    const int bm = blockIdx.x * 128;
    const int bn = blockIdx.y * 128;
    const int gcBase = blockIdx.z * chunksPerZ;
    float* Cz = C + (size_t)blockIdx.z * M * N;

    const int lrow = tid >> 1;
    const int lcolB = (tid & 1) * 64;
    const __half* Arow = A + (size_t)(bm + lrow) * KA;
    const __half* Brow = Bt + (size_t)(bn + lrow) * KB;
    uint32_t st[4];
#pragma unroll
    for (int j = 0; j < 4; j++) {
        uint32_t o = (uint32_t)lrow * 128u + (uint32_t)lcolB + j * 16u;
        st[j] = SWZ128(o);
    }

    const int l8 = lane & 7;
    const int rowA = wm * 32 + ((lane >> 3) & 1) * 8 + l8;
    const uint32_t colA = (uint32_t)((lane >> 4) * 16);
    const uint32_t xorA = (uint32_t)((rowA & 7) << 4);
    const int rowB = wn * 64 + ((lane >> 4) & 1) * 8 + l8;
    const uint32_t colB = (uint32_t)(((lane >> 3) & 1) * 16);
    const uint32_t xorB = (uint32_t)((rowB & 7) << 4);

    float c[2][8][4];
#pragma unroll
    for (int mf = 0; mf < 2; mf++)
#pragma unroll
        for (int nf = 0; nf < 8; nf++)
#pragma unroll
            for (int i = 0; i < 4; i++) c[mf][nf][i] = 0.f;

    auto issue = [&](int gc, int s) {
        int bc = (gc < P) ? gc : gc - P;
        const unsigned char* Ag = (const unsigned char*)(Arow + gc * 64);
        const unsigned char* Bg = (const unsigned char*)(Brow + bc * 64);
        uint32_t ab = sb + (uint32_t)s * 32768u;
        uint32_t bb = ab + 16384u;
#pragma unroll
        for (int j = 0; j < 4; j++) cpasync16(ab + st[j], Ag + lcolB + j * 16);
#pragma unroll
        for (int j = 0; j < 4; j++) cpasync16(bb + st[j], Bg + lcolB + j * 16);
    };

#pragma unroll
    for (int p = 0; p < 2; p++) {
        issue(gcBase + p, p);
        CP_COMMIT();
    }

    int sc = 0;
    int sp = 2;

    for (int i = 0; i < chunksPerZ; i++) {
        CP_WAIT1();
        __syncthreads();

        if (i + 2 < chunksPerZ) issue(gcBase + i + 2, sp);
        CP_COMMIT();

        uint32_t ab = sb + (uint32_t)sc * 32768u;
        uint32_t bb = ab + 16384u;
#pragma unroll
        for (int ks = 0; ks < 4; ks++) {
            uint32_t af0[4], af1[4];
            uint32_t ac = ((uint32_t)(ks * 32) + colA) ^ xorA;
            ldm4(af0, ab + (uint32_t)rowA * 128u + ac);
            ldm4(af1, ab + (uint32_t)rowA * 128u + 2048u + ac);

            uint32_t bf[4][4];
            uint32_t bc = ((uint32_t)(ks * 32) + colB) ^ xorB;
#pragma unroll
            for (int p = 0; p < 4; p++)
                ldm4(bf[p], bb + (uint32_t)(rowB + p * 16) * 128u + bc);

#pragma unroll
            for (int nf = 0; nf < 8; nf++) {
                uint32_t b0 = bf[nf >> 1][(nf & 1) * 2 + 0];
                uint32_t b1 = bf[nf >> 1][(nf & 1) * 2 + 1];
                mma16816(c[0][nf], af0, b0, b1);
                mma16816(c[1][nf], af1, b0, b1);
            }
        }

        sc = (sc == 2) ? 0 : sc + 1;
        sp = (sp == 2) ? 0 : sp + 1;
    }

    const int g  = lane >> 2;
    const int t4 = lane & 3;
#pragma unroll
    for (int mf = 0; mf < 2; mf++) {
#pragma unroll
        for (int nf = 0; nf < 8; nf++) {
            int row = bm + wm * 32 + mf * 16 + g;
            int col = bn + wn * 64 + nf * 8 + t4 * 2;
            *(float2*)(Cz + (size_t)row * N + col)       = make_float2(c[mf][nf][0], c[mf][nf][1]);
            *(float2*)(Cz + (size_t)(row + 8) * N + col) = make_float2(c[mf][nf][2], c[mf][nf][3]);
        }
    }
}

__global__ __launch_bounds__(256) void combine_kernel(const float* __restrict__ c012, float* __restrict__ out)
{
    int i = blockIdx.x * 256 + threadIdx.x;
    const size_t S = (size_t)T_LEN * HID;
    out[i] = c012[i] + c012[i + S] + c012[i + 2 * S];
}

// ---------------- fp16 hi/lo split ----------------
__device__ __forceinline__ void f16split(float x, __half& hi, __half& lo) {
    hi = __float2half_rn(x);
    lo = __float2half_rn(x - __half2float(hi));
}

// ---------------- merged prep kernel ----------------
#define NB_SPLIT 2048
#define NB_TSP   ((HID/64)*(PROJN_PAD/32))
#define NB_TSW   ((VDIM/64)*(HID/32))

__device__ void split_hs_body(const float* __restrict__ hs, __half* __restrict__ A3, int b)
{
    int idx = b * 256 + threadIdx.x;
    int t = idx >> 9;
    int kq = (idx & 511) * 4;
    float4 x = *(const float4*)(hs + (size_t)t * HID + kq);
    __half2 h01, h23, l01, l23;
    __half h, l;
    f16split(x.x, h, l); h01.x = h; l01.x = l;
    f16split(x.y, h, l); h01.y = h; l01.y = l;
    f16split(x.z, h, l); h23.x = h; l23.x = l;
    f16split(x.w, h, l); h23.y = h; l23.y = l;
    __half* row = A3 + (size_t)t * KA1;
    *(__half2*)(row + kq)           = h01;
    *(__half2*)(row + kq + 2)       = h23;
    *(__half2*)(row + HID + kq)     = l01;
    *(__half2*)(row + HID + kq + 2) = l23;
}

template<int KW>
__device__ __forceinline__ void tstore_tile(
    const float* tileflat, int k0, int n0, __half* Bout)
{
    const float (*tile)[72] = (const float (*)[72])tileflat;
    int tid = threadIdx.x;
#pragma unroll
    for (int pass = 0; pass < 4; pass++) {
        int nl = (tid >> 5) + pass * 8;
        int kl = (tid & 31) * 2;
        __half2 hp;
        hp.x = __float2half_rn(tile[nl][kl]);
        hp.y = __float2half_rn(tile[nl][kl + 1]);
        *reinterpret_cast<__half2*>(Bout + (size_t)(n0 + nl) * KW + k0 + kl) = hp;
    }
}

__device__ void tsplit_proj_body(
    const float* __restrict__ Wq, const float* __restrict__ Wk,
    const float* __restrict__ Wv, const float* __restrict__ Wg,
    const float* __restrict__ Wb, const float* __restrict__ Wa,
    __half* __restrict__ B3, int bx, int by)
{
    __shared__ float tile[32][72];
    int k0 = bx * 64, n0 = by * 32;
    int tid = threadIdx.x;
    int nl = tid & 31, n = n0 + nl;
#pragma unroll
    for (int i = 0; i < 8; i++) {
        int k = k0 + (tid >> 5) + i * 8;
        float v;
        if      (n < KDIM)            v = Wq[(size_t)k * KDIM + n];
        else if (n < 2 * KDIM)        v = Wk[(size_t)k * KDIM + n - KDIM];
        else if (n < 2 * KDIM + VDIM) v = Wv[(size_t)k * VDIM + n - 2 * KDIM];
        else if (n < PROJN)           v = Wg[(size_t)k * VDIM + n - 2 * KDIM - VDIM];
        else if (n < PROJN + NH)      v = Wb[(size_t)k * NH + n - PROJN];
        else if (n < PROJN + 2 * NH)  v = Wa[(size_t)k * NH + n - PROJN - NH];
        else                          v = 0.f;
        tile[nl][(tid >> 5) + i * 8] = v;
    }
    __syncthreads();
    tstore_tile<KB1>(&tile[0][0], k0, n0, B3);
}

__device__ void tsplit_wo_body(const float* __restrict__ Wo, __half* __restrict__ B2, int bx, int by)
{
    __shared__ float tile[32][72];
    int k0 = bx * 64, n0 = by * 32;
    int tid = threadIdx.x;
    int nl = tid & 31;
#pragma unroll
    for (int i = 0; i < 8; i++) {
        int k = k0 + (tid >> 5) + i * 8;
        tile[nl][(tid >> 5) + i * 8] = Wo[(size_t)k * HID + n0 + nl];
    }
    __syncthreads();
    tstore_tile<KB2>(&tile[0][0], k0, n0, B2);
}

__global__ __launch_bounds__(256) void prep_all(
    const float* __restrict__ hs,
    const float* __restrict__ Wq, const float* __restrict__ Wk,
    const float* __restrict__ Wv, const float* __restrict__ Wg,
    const float* __restrict__ Wb, const float* __restrict__ Wa,
    const float* __restrict__ Wo,
    __half* __restrict__ A3, __half* __restrict__ B3, __half* __restrict__ B2)
{
    int b = blockIdx.x;
    if (b < NB_SPLIT) {
        split_hs_body(hs, A3, b);
    } else if (b < NB_SPLIT + NB_TSP) {
        int bb = b - NB_SPLIT;
        tsplit_proj_body(Wq, Wk, Wv, Wg, Wb, Wa, B3, bb % (HID / 64), bb / (HID / 64));
    } else {
        int bb = b - NB_SPLIT - NB_TSP;
        tsplit_wo_body(Wo, B2, bb % (VDIM / 64), bb / (VDIM / 64));
    }
}

// ---------------- fused conv (+ beta/g fold on h==0 blocks) ----------------
__global__ __launch_bounds__(256) void conv_fused(
    const float* __restrict__ proj,
    const float* __restrict__ wq, const float* __restrict__ wk, const float* __restrict__ wv,
    const float* __restrict__ A_log, const float* __restrict__ dt_bias,
    float* __restrict__ qo, float* __restrict__ ko, float* __restrict__ vo,
    float* __restrict__ beta, float* __restrict__ egout)
{
    int t = blockIdx.x, h = blockIdx.y;
    int d = threadIdx.x;
    int which = d >> 7;
    int dd = d & 127;
    int ch = h * DK + dd;

    const float* w = which ? wk : wq;
    int cqk = (which ? KDIM : 0) + ch;
    int cv  = 2 * KDIM + h * DV + d;

    float y = 0.f, yv = 0.f;
#pragma unroll
    for (int i = 0; i < 4; i++) {
        int tt = t - 3 + i;
        if (tt >= 0) {
            const float* prow = proj + (size_t)tt * PROJN_PAD;
            y  = fmaf(prow[cqk], w[ch * 4 + i], y);
            yv = fmaf(prow[cv], wv[(h * DV + d) * 4 + i], yv);
        }
    }
    y  = y / (1.f + expf(-y));
    yv = yv / (1.f + expf(-yv));

    float ss = y * y;
#pragma unroll
    for (int off = 16; off; off >>= 1)
        ss += __shfl_xor_sync(0xffffffffu, ss, off);
    __shared__ float red[8];
    int lane = d & 31, warp = d >> 5;
    if (lane == 0) red[warp] = ss;
    __syncthreads();
    float tot = red[which * 4 + 0] + red[which * 4 + 1] + red[which * 4 + 2] + red[which * 4 + 3];

    float* dst = which ? ko : qo;
    dst[(size_t)t * KDIM + ch] = y * rsqrtf(tot + 1e-6f);
    vo[(size_t)t * VDIM + h * DV + d] = yv;

    if (h == 0 && d < 24) {
        float sv = proj[(size_t)t * PROJN_PAD + PROJN + d];
        if (d < NH) {
            beta[t * NH + d] = 1.f / (1.f + expf(-sv));
        } else {
            int hh = d - NH;
            float x = sv + dt_bias[hh];
            float sp = (x > 20.f) ? x : log1pf(expf(x));
            egout[t * NH + hh] = expf(-expf(A_log[hh]) * sp);
        }
    }
}

// ---------------- block-processed gated delta-rule scan (B=8), v7 ----------------
// v6 + redundant solver on ALL warps: dlt chain recomputed per warp from smem
// (identical inputs -> identical results), so no dltsh/wsh/E7sh broadcast and
// barriers C and D are eliminated. 3 barriers/block.
#define KQPAD 132
#define NBLK 128

__global__ __launch_bounds__(256, 1) void scan_block_kernel(
    const float* __restrict__ q, const float* __restrict__ k,
    const float* __restrict__ v, const float* __restrict__ eg_in,
    const float* __restrict__ bb, float* __restrict__ o)
{
    const int h = blockIdx.x >> 3;
    const int chunk = blockIdx.x & 7;
    const int tid = threadIdx.x;
    const int j = tid & 31;
    const int g = tid >> 5;
    const int G = g * 16;

    __shared__ float kqsh[2][2][8][KQPAD];   // [0=k,1=q][buf][step][dim(128)+pad]
    __shared__ float vsh[2][8][32];
    __shared__ float egb[2][2][8];
    __shared__ float pdk[8][32 * 9];
    __shared__ float pdq[8][32 * 9];
    __shared__ float psc[64][9];
    __shared__ float ar[8][33], br[8][33];
    __shared__ float scal[64];

    float S[16];
#pragma unroll
    for (int i = 0; i < 16; i++) S[i] = 0.f;
    float4 kr[8][4];

    const int kq_base = h * DK;
    const int v_base  = h * DV + chunk * 32;

    const int ki  = tid >> 5;
    const int kf  = (tid & 31) * 4;
    const int vi  = tid >> 3;
    const int vf  = (tid & 7) * 4;
    uint32_t kdst[2], qdst[2], vdst[2];
#pragma unroll
    for (int p = 0; p < 2; p++) {
        kdst[p] = smem_u32(&kqsh[0][p][ki][kf]);
        qdst[p] = smem_u32(&kqsh[1][p][ki][kf]);
        vdst[p] = smem_u32(&vsh[p][0][0]) + (uint32_t)(vi * 32 + vf) * 4u;
    }

    const int eb_i = tid - 192;
    float pebs = 0.f;
    if (eb_i >= 0 && eb_i < 16) {
        int i0 = eb_i & 7;
        pebs = (eb_i < 8) ? eg_in[(size_t)i0 * NH + h] : bb[(size_t)i0 * NH + h];
    }

    const unsigned e0 = PAIR_TAB[j];
    const unsigned e1 = PAIR_TAB[j + 32];
    const int q0_ = e0 >> 6, si0 = (e0 >> 3) & 7, ss0 = e0 & 7;
    const int q1_ = e1 >> 6, si1 = (e1 >> 3) & 7, ss1 = e1 & 7;

    {
        cpasync16(kdst[0], k + (size_t)ki * KDIM + kq_base + kf);
        cpasync16(qdst[0], q + (size_t)ki * KDIM + kq_base + kf);
        if (tid < 64) cpasync16(vdst[0], v + (size_t)vi * VDIM + v_base + vf);
        CP_COMMIT();
    }

    for (int b = 0; b < NBLK; b++) {
        const int buf = b & 1;
        const int t0 = b * 8;

        CP_WAIT0();
        if (eb_i >= 0 && eb_i < 16)
            egb[buf][eb_i >> 3][eb_i & 7] = pebs;
        __syncthreads();                                   // (A)

        if (b + 1 < NBLK) {
            const int nb = (b + 1) & 1;
            const size_t r0 = (size_t)(t0 + 8);
            cpasync16(kdst[nb], k + (r0 + ki) * KDIM + kq_base + kf);
            cpasync16(qdst[nb], q + (r0 + ki) * KDIM + kq_base + kf);
            if (tid < 64) cpasync16(vdst[nb], v + (r0 + vi) * VDIM + v_base + vf);
            if (eb_i >= 0 && eb_i < 16) {
                int i0 = eb_i & 7;
                pebs = (eb_i < 8) ? eg_in[(r0 + i0) * NH + h] : bb[(r0 + i0) * NH + h];
            }
            CP_COMMIT();
        }

        // ---- P1: vector partials; cache k segment in registers ----
#pragma unroll
        for (int i = 0; i < 8; i++) {
            float pk = 0.f, pq = 0.f;
#pragma unroll
            for (int r4 = 0; r4 < 4; r4++) {
                kr[i][r4] = *(const float4*)&kqsh[0][buf][i][G + r4 * 4];
                float4 qv = *(const float4*)&kqsh[1][buf][i][G + r4 * 4];
                float4 kv = kr[i][r4];
                pk = fmaf(kv.x, S[r4*4+0], pk); pk = fmaf(kv.y, S[r4*4+1], pk);
                pk = fmaf(kv.z, S[r4*4+2], pk); pk = fmaf(kv.w, S[r4*4+3], pk);
                pq = fmaf(qv.x, S[r4*4+0], pq); pq = fmaf(qv.y, S[r4*4+1], pq);
                pq = fmaf(qv.z, S[r4*4+2], pq); pq = fmaf(qv.w, S[r4*4+3], pq);
            }
            pdk[i][j * 9 + g] = pk;
            pdq[i][j * 9 + g] = pq;
        }

        // ---- P1b: 64 triangular pair dots (conflict-free via KQPAD) ----
        {
            float s0 = 0.f, s1 = 0.f;
            const float* a0 = &kqsh[q0_][buf][si0][G];
            const float* c0 = &kqsh[0][buf][ss0][G];
            const float* a1 = &kqsh[q1_][buf][si1][G];
            const float* c1 = &kqsh[0][buf][ss1][G];
#pragma unroll
            for (int r4 = 0; r4 < 4; r4++) {
                float4 av = *(const float4*)(a0 + r4 * 4);
                float4 cv = *(const float4*)(c0 + r4 * 4);
                s0 = fmaf(av.x, cv.x, s0); s0 = fmaf(av.y, cv.y, s0);
                s0 = fmaf(av.z, cv.z, s0); s0 = fmaf(av.w, cv.w, s0);
                float4 av1 = *(const float4*)(a1 + r4 * 4);
                float4 cv1 = *(const float4*)(c1 + r4 * 4);
                s1 = fmaf(av1.x, cv1.x, s1); s1 = fmaf(av1.y, cv1.y, s1);
                s1 = fmaf(av1.z, cv1.z, s1); s1 = fmaf(av1.w, cv1.w, s1);
            }
            psc[j][g] = s0;
            psc[j + 32][g] = s1;
        }
        __syncthreads();                                   // (B)

        // ---- distributed reductions ----
        {
            float sa = 0.f, sb2 = 0.f;
#pragma unroll
            for (int gg = 0; gg < 8; gg++) {
                sa  += pdk[g][j * 9 + gg];
                sb2 += pdq[g][j * 9 + gg];
            }
            ar[g][j] = sa;
            br[g][j] = sb2;
            if (tid < 64) {
                float sv = 0.f;
#pragma unroll
                for (int gg = 0; gg < 8; gg++) sv += psc[tid][gg];
                scal[tid] = sv;
            }
        }
        __syncthreads();                                   // (B2)

        // ---- redundant solver (every warp; identical results) ----
        float eg[8], bet[8], E[8];
        {
            float Ec = 1.f;
#pragma unroll
            for (int i = 0; i < 8; i++) {
                eg[i]  = egb[buf][0][i];
                bet[i] = egb[buf][1][i];
                Ec *= eg[i];
                E[i] = Ec;
            }
        }
        float dlt[8];
#pragma unroll
        for (int i = 0; i < 8; i++) {
            float acc = vsh[buf][i][j] - E[i] * ar[i][j];
            float rr = 1.f;
#pragma unroll
            for (int s = i - 1; s >= 0; s--) {
                rr *= eg[s + 1];
                acc -= rr * scal[TK(i, s)] * dlt[s];
            }
            dlt[i] = bet[i] * acc;
        }

        // ---- o: warp g writes step i=g for its 32 columns (local dlt) ----
        {
            const int i = g;
            float oacc = fmaf(E[i], br[i][j], scal[TQ(i, i)] * dlt[i]);
            float rr = 1.f;
#pragma unroll
            for (int s = 6; s >= 0; s--) {
                if (s < i) {
                    rr *= eg[s + 1];
                    oacc = fmaf(rr * scal[TQ(i, s)], dlt[s], oacc);
                }
            }
            o[(size_t)(t0 + i) * VDIM + v_base + j] = oacc;
        }

        // ---- P5: rank-8 state update with local w[s] = r_{7,s} * dlt[s] ----
        {
            float w[8];
            float rr = 1.f;
#pragma unroll
            for (int s = 7; s >= 0; s--) {
                w[s] = rr * dlt[s];
                rr *= eg[s];
            }
            float E7 = E[7];
#pragma unroll
            for (int r = 0; r < 16; r++) S[r] *= E7;
#pragma unroll
            for (int s = 0; s < 8; s++) {
#pragma unroll
                for (int r4 = 0; r4 < 4; r4++) {
                    float4 kv = kr[s][r4];
                    S[r4*4+0] = fmaf(kv.x, w[s], S[r4*4+0]);
                    S[r4*4+1] = fmaf(kv.y, w[s], S[r4*4+1]);
                    S[r4*4+2] = fmaf(kv.z, w[s], S[r4*4+2]);
                    S[r4*4+3] = fmaf(kv.w, w[s], S[r4*4+3]);
                }
            }
        }
        // next block's barrier (A) orders ar/br/scal reuse
    }
}

// ---------------- RMSNorm * norm_w * SiLU(gate) -> A2 f16 [hi | lo] ----------------
__global__ __launch_bounds__(256) void epilogue_kernel(
    const float* __restrict__ o, const float* __restrict__ proj,
    const float* __restrict__ norm_w, __half* __restrict__ A2)
{
    int t = blockIdx.x, h = blockIdx.y;
    int d = threadIdx.x;
    float x = o[(size_t)t * VDIM + h * DV + d];

    float ss = x * x;
#pragma unroll
    for (int off = 16; off; off >>= 1)
        ss += __shfl_xor_sync(0xffffffffu, ss, off);
    __shared__ float red[8];
    int lane = threadIdx.x & 31, warp = threadIdx.x >> 5;
    if (lane == 0) red[warp] = ss;
    __syncthreads();
    float tot = 0.f;
#pragma unroll
    for (int w = 0; w < 8; w++) tot += red[w];

    float scale = rsqrtf(tot * (1.f / 256.f) + 1e-5f);
    float gg = proj[(size_t)t * PROJN_PAD + 2 * KDIM + VDIM + h * DV + d];
    float silu_g = gg / (1.f + expf(-gg));
    float val = x * scale * norm_w[d] * silu_g;

    __half hi, lo;
    f16split(val, hi, lo);
    __half* row = A2 + (size_t)t * KA2;
    int col = h * DV + d;
    row[col] = hi; row[VDIM + col] = lo;
}

// ---------------- launch ----------------
extern "C" void kernel_launch(void* const* d_in, const int* in_sizes, int n_in,
                              void* d_out, int out_size)
{
    const float* hs      = (const float*)d_in[0];
    const float* Wq      = (const float*)d_in[1];
    const float* Wk      = (const float*)d_in[2];
    const float* Wv      = (const float*)d_in[3];
    const float* Wb      = (const float*)d_in[4];
    const float* Wa      = (const float*)d_in[5];
    const float* Wg      = (const float*)d_in[6];
    const float* Wo      = (const float*)d_in[7];
    const float* conv_wq = (const float*)d_in[8];
    const float* conv_wk = (const float*)d_in[9];
    const float* conv_wv = (const float*)d_in[10];
    const float* A_log   = (const float*)d_in[11];
    const float* dt_bias = (const float*)d_in[12];
    const float* norm_w  = (const float*)d_in[13];
    float* out = (float*)d_out;

    unsigned char* s = nullptr;
    cudaGetSymbolAddress((void**)&s, g_scratch);
    float*   PROJ  = (float*)(s + B_PROJ);
    __half*  A3    = (__half*)(s + B_A3);
    __half*  B3    = (__half*)(s + B_B3);
    __half*  A2    = (__half*)(s + B_A2);
    __half*  B2    = (__half*)(s + B_B2);
    float*   Qb    = (float*)(s + B_Q);
    float*   Kb    = (float*)(s + B_K);
    float*   Vb    = (float*)(s + B_V);
    float*   Ob    = (float*)(s + B_O);
    float*   Gb    = (float*)(s + B_G);
    float*   Bb    = (float*)(s + B_BB);
    float*   Cpart = (float*)(s + B_CP);

    cudaFuncSetAttribute(gemm_f16, cudaFuncAttributeMaxDynamicSharedMemorySize, GEMM_SMEM);

    // 1) merged prep
    prep_all<<<NB_SPLIT + NB_TSP + NB_TSW, 256>>>(hs, Wq, Wk, Wv, Wg, Wb, Wa, Wo, A3, B3, B2);

    // 2) projection GEMM: 128x128 tiles, logical 2P = 64 chunks (P = 32)
    gemm_f16<<<dim3(T_LEN / 128, PROJN_PAD / 128, 1), 256, GEMM_SMEM>>>(
        A3, B3, PROJ, T_LEN, PROJN_PAD, KA1, KB1, 32, 64);

    // 3) fused convs + beta/exp(g)
    conv_fused<<<dim3(T_LEN, NH), 256>>>(PROJ, conv_wq, conv_wk, conv_wv,
                                         A_log, dt_bias, Qb, Kb, Vb, Bb, Gb);

    // 4) scan (3 barriers/block)
    scan_block_kernel<<<NH * 8, 256>>>(Qb, Kb, Vb, Gb, Bb, Ob);

    // 5) epilogue
    epilogue_kernel<<<dim3(T_LEN, NH), 256>>>(Ob, PROJ, norm_w, A2);

    // 6) output GEMM: logical 2P = 96 chunks (P = 48), split-K = 3
    gemm_f16<<<dim3(T_LEN / 128, HID / 128, 3), 256, GEMM_SMEM>>>(
        A2, B2, Cpart, T_LEN, HID, KA2, KB2, 48, 32);
    combine_kernel<<<(T_LEN * HID) / 256, 256>>>(Cpart, out);
}